// round 1
// baseline (speedup 1.0000x reference)
#include <cuda_runtime.h>
#include <cuda_bf16.h>
#include <cstdint>

// Problem constants (fixed by the dataset)
#define NN 50000
#define EE 800000
#define F 128
#define CC 4

// ---------------- device scratch (no allocation allowed) ----------------
__device__ __align__(128) int   g_cnt[NN];
__device__ __align__(128) int   g_fill[NN];
__device__ __align__(128) int   g_ptr[NN + 1];
__device__ __align__(128) int   g_idx[EE];
__device__ __align__(128) int   g_partial[NN];
__device__ __align__(128) int   g_bsum[256];
__device__ __align__(128) float g_invd[NN];
__device__ __align__(128) float g_y[(size_t)NN * F];
__device__ __align__(128) float g_r[(size_t)NN * F];
__device__ __align__(128) float g_h[(size_t)NN * F];
__device__ __align__(128) float g_z[(size_t)NN * CC];
__device__ __align__(128) float g_r2[(size_t)NN * CC];

// ---------------- CSR build ----------------
__global__ void k_init(int n) {
    int i = blockIdx.x * blockDim.x + threadIdx.x;
    if (i < n) { g_cnt[i] = 0; g_fill[i] = 0; }
}

__global__ void k_hist(const int* __restrict__ dst, int e) {
    int i = blockIdx.x * blockDim.x + threadIdx.x;
    if (i < e) atomicAdd(&g_cnt[dst[i]], 1);
}

#define SCAN_B 512
__global__ void k_scan1(int n) {
    __shared__ int s[SCAN_B];
    int i = blockIdx.x * SCAN_B + threadIdx.x;
    int v = (i < n) ? g_cnt[i] : 0;
    s[threadIdx.x] = v;
    __syncthreads();
    #pragma unroll
    for (int off = 1; off < SCAN_B; off <<= 1) {
        int t = (threadIdx.x >= off) ? s[threadIdx.x - off] : 0;
        __syncthreads();
        s[threadIdx.x] += t;
        __syncthreads();
    }
    if (i < n) g_partial[i] = s[threadIdx.x];
    if (threadIdx.x == SCAN_B - 1) g_bsum[blockIdx.x] = s[threadIdx.x];
}

__global__ void k_scan2(int nb) {  // single block, 256 threads
    __shared__ int s[256];
    int v = (threadIdx.x < nb) ? g_bsum[threadIdx.x] : 0;
    s[threadIdx.x] = v;
    __syncthreads();
    #pragma unroll
    for (int off = 1; off < 256; off <<= 1) {
        int t = (threadIdx.x >= off) ? s[threadIdx.x - off] : 0;
        __syncthreads();
        s[threadIdx.x] += t;
        __syncthreads();
    }
    if (threadIdx.x < nb) g_bsum[threadIdx.x] = s[threadIdx.x] - v;  // exclusive
}

__global__ void k_scan3(int n) {  // same geometry as k_scan1
    int i = blockIdx.x * SCAN_B + threadIdx.x;
    if (i < n) {
        int inc = g_partial[i] + g_bsum[blockIdx.x];
        g_ptr[i + 1] = inc;
        int c = g_cnt[i];
        g_invd[i] = (c > 0) ? (1.0f / (float)c) : 0.0f;
        if (i == 0) g_ptr[0] = 0;
    }
}

__global__ void k_fill(const int* __restrict__ src, const int* __restrict__ dst, int e) {
    int i = blockIdx.x * blockDim.x + threadIdx.x;
    if (i < e) {
        int d = dst[i];
        int p = g_ptr[d] + atomicAdd(&g_fill[d], 1);
        g_idx[p] = src[i];
    }
}

// ---------------- SGEMM: C[M,128] = A[M,128] @ W[128,128]  (two W per launch) ----------------
#define BM 128
#define BN 128
#define BK 8
__global__ __launch_bounds__(256, 2)
void k_sgemm(const float* __restrict__ A,
             const float* __restrict__ Wl, const float* __restrict__ Wr,
             float* __restrict__ Yl, float* __restrict__ Yr, int M) {
    const float* B = blockIdx.y ? Wr : Wl;
    float* C = blockIdx.y ? Yr : Yl;

    __shared__ float As[BK][BM];
    __shared__ float Bs[BK][BN];

    int tid = threadIdx.x;          // 256 threads
    int tx = tid & 15;              // 0..15
    int ty = tid >> 4;              // 0..15
    int rowBase = blockIdx.x * BM;

    float acc[8][8];
    #pragma unroll
    for (int i = 0; i < 8; i++)
        #pragma unroll
        for (int j = 0; j < 8; j++) acc[i][j] = 0.0f;

    int aRow = tid >> 1;            // 0..127
    int aCol = (tid & 1) * 4;       // 0 or 4
    int bRow = tid >> 5;            // 0..7
    int bCol = (tid & 31) * 4;      // 0..124

    for (int k0 = 0; k0 < F; k0 += BK) {
        int gRow = rowBase + aRow;
        float4 av = make_float4(0.f, 0.f, 0.f, 0.f);
        if (gRow < M) av = *(const float4*)(A + (size_t)gRow * F + k0 + aCol);
        As[aCol + 0][aRow] = av.x;
        As[aCol + 1][aRow] = av.y;
        As[aCol + 2][aRow] = av.z;
        As[aCol + 3][aRow] = av.w;
        float4 bv = *(const float4*)(B + (size_t)(k0 + bRow) * BN + bCol);
        *(float4*)(&Bs[bRow][bCol]) = bv;
        __syncthreads();
        #pragma unroll
        for (int k = 0; k < BK; k++) {
            float ra[8], rb[8];
            float4 t;
            t = *(float4*)(&As[k][ty * 4]);       ra[0]=t.x; ra[1]=t.y; ra[2]=t.z; ra[3]=t.w;
            t = *(float4*)(&As[k][64 + ty * 4]);  ra[4]=t.x; ra[5]=t.y; ra[6]=t.z; ra[7]=t.w;
            t = *(float4*)(&Bs[k][tx * 4]);       rb[0]=t.x; rb[1]=t.y; rb[2]=t.z; rb[3]=t.w;
            t = *(float4*)(&Bs[k][64 + tx * 4]);  rb[4]=t.x; rb[5]=t.y; rb[6]=t.z; rb[7]=t.w;
            #pragma unroll
            for (int i = 0; i < 8; i++)
                #pragma unroll
                for (int j = 0; j < 8; j++)
                    acc[i][j] += ra[i] * rb[j];
        }
        __syncthreads();
    }

    #pragma unroll
    for (int i = 0; i < 8; i++) {
        int r = rowBase + ((i < 4) ? (ty * 4 + i) : (64 + ty * 4 + i - 4));
        if (r < M) {
            *(float4*)(C + (size_t)r * BN + tx * 4)      = make_float4(acc[i][0], acc[i][1], acc[i][2], acc[i][3]);
            *(float4*)(C + (size_t)r * BN + 64 + tx * 4) = make_float4(acc[i][4], acc[i][5], acc[i][6], acc[i][7]);
        }
    }
}

// ---------------- 128-wide aggregation, fused epilogue ----------------
// O[n] = relu?( (sum_{nb in N(n)} Y[nb]) * invd[n] + bias + R[n] )
__global__ void k_agg128(const float* __restrict__ Y, const float* __restrict__ R,
                         const float* __restrict__ bias, float* __restrict__ O,
                         int n, int doRelu) {
    int gwarp = (blockIdx.x * blockDim.x + threadIdx.x) >> 5;
    int lane = threadIdx.x & 31;
    if (gwarp >= n) return;
    int s = g_ptr[gwarp], e = g_ptr[gwarp + 1];
    float4 a0 = make_float4(0.f, 0.f, 0.f, 0.f);
    float4 a1 = make_float4(0.f, 0.f, 0.f, 0.f);
    int i = s;
    for (; i + 1 < e; i += 2) {
        int n0 = g_idx[i], n1 = g_idx[i + 1];
        float4 v0 = *(const float4*)(Y + (size_t)n0 * F + lane * 4);
        float4 v1 = *(const float4*)(Y + (size_t)n1 * F + lane * 4);
        a0.x += v0.x; a0.y += v0.y; a0.z += v0.z; a0.w += v0.w;
        a1.x += v1.x; a1.y += v1.y; a1.z += v1.z; a1.w += v1.w;
    }
    if (i < e) {
        int n0 = g_idx[i];
        float4 v0 = *(const float4*)(Y + (size_t)n0 * F + lane * 4);
        a0.x += v0.x; a0.y += v0.y; a0.z += v0.z; a0.w += v0.w;
    }
    a0.x += a1.x; a0.y += a1.y; a0.z += a1.z; a0.w += a1.w;
    float id = g_invd[gwarp];
    float4 rv = *(const float4*)(R + (size_t)gwarp * F + lane * 4);
    float4 bv = *(const float4*)(bias + lane * 4);
    float4 o;
    o.x = a0.x * id + bv.x + rv.x;
    o.y = a0.y * id + bv.y + rv.y;
    o.z = a0.z * id + bv.z + rv.z;
    o.w = a0.w * id + bv.w + rv.w;
    if (doRelu) {
        o.x = fmaxf(o.x, 0.f); o.y = fmaxf(o.y, 0.f);
        o.z = fmaxf(o.z, 0.f); o.w = fmaxf(o.w, 0.f);
    }
    *(float4*)(O + (size_t)gwarp * F + lane * 4) = o;
}

// ---------------- small GEMM: Z[M,4] = H[M,128] @ Wl2, R2 = H @ Wr2 ----------------
__global__ void k_gemm_small(const float* __restrict__ H,
                             const float* __restrict__ Wl, const float* __restrict__ Wr,
                             int M) {
    __shared__ float sWl[F * CC];
    __shared__ float sWr[F * CC];
    int tid = threadIdx.x;
    for (int i = tid; i < F * CC; i += blockDim.x) { sWl[i] = Wl[i]; sWr[i] = Wr[i]; }
    __syncthreads();
    int gwarp = (blockIdx.x * blockDim.x + tid) >> 5;
    int lane = tid & 31;
    if (gwarp >= M) return;
    float4 h = *(const float4*)(H + (size_t)gwarp * F + lane * 4);
    float hv[4] = {h.x, h.y, h.z, h.w};
    float zl[4] = {0.f, 0.f, 0.f, 0.f};
    float zr[4] = {0.f, 0.f, 0.f, 0.f};
    #pragma unroll
    for (int kk = 0; kk < 4; kk++) {
        int k = lane * 4 + kk;
        #pragma unroll
        for (int j = 0; j < 4; j++) {
            zl[j] += hv[kk] * sWl[k * CC + j];
            zr[j] += hv[kk] * sWr[k * CC + j];
        }
    }
    #pragma unroll
    for (int off = 16; off > 0; off >>= 1) {
        #pragma unroll
        for (int j = 0; j < 4; j++) {
            zl[j] += __shfl_down_sync(0xFFFFFFFFu, zl[j], off);
            zr[j] += __shfl_down_sync(0xFFFFFFFFu, zr[j], off);
        }
    }
    if (lane == 0) {
        *(float4*)(g_z  + (size_t)gwarp * CC) = make_float4(zl[0], zl[1], zl[2], zl[3]);
        *(float4*)(g_r2 + (size_t)gwarp * CC) = make_float4(zr[0], zr[1], zr[2], zr[3]);
    }
}

// ---------------- 4-wide aggregation + final epilogue; writes out twice ----------------
__global__ void k_agg4(const float* __restrict__ b2, float* __restrict__ out, int n) {
    int gwarp = (blockIdx.x * blockDim.x + threadIdx.x) >> 5;
    int lane = threadIdx.x & 31;
    if (gwarp >= n) return;
    int s = g_ptr[gwarp], e = g_ptr[gwarp + 1];
    float4 acc = make_float4(0.f, 0.f, 0.f, 0.f);
    for (int i = s + lane; i < e; i += 32) {
        int nb = g_idx[i];
        float4 z = *(const float4*)(g_z + (size_t)nb * CC);
        acc.x += z.x; acc.y += z.y; acc.z += z.z; acc.w += z.w;
    }
    #pragma unroll
    for (int off = 16; off > 0; off >>= 1) {
        acc.x += __shfl_xor_sync(0xFFFFFFFFu, acc.x, off);
        acc.y += __shfl_xor_sync(0xFFFFFFFFu, acc.y, off);
        acc.z += __shfl_xor_sync(0xFFFFFFFFu, acc.z, off);
        acc.w += __shfl_xor_sync(0xFFFFFFFFu, acc.w, off);
    }
    if (lane == 0) {
        float id = g_invd[gwarp];
        float4 r = *(const float4*)(g_r2 + (size_t)gwarp * CC);
        float4 b = *(const float4*)(b2);
        float4 o;
        o.x = acc.x * id + b.x + r.x;
        o.y = acc.y * id + b.y + r.y;
        o.z = acc.z * id + b.z + r.z;
        o.w = acc.w * id + b.w + r.w;
        *(float4*)(out + (size_t)gwarp * CC) = o;
        *(float4*)(out + (size_t)n * CC + (size_t)gwarp * CC) = o;
    }
}

// ---------------- launch ----------------
extern "C" void kernel_launch(void* const* d_in, const int* in_sizes, int n_in,
                              void* d_out, int out_size) {
    const float* x   = (const float*)d_in[0];
    const int*   ei  = (const int*)d_in[1];
    const float* Wl0 = (const float*)d_in[2];
    const float* bl0 = (const float*)d_in[3];
    const float* Wr0 = (const float*)d_in[4];
    const float* Wl1 = (const float*)d_in[5];
    const float* bl1 = (const float*)d_in[6];
    const float* Wr1 = (const float*)d_in[7];
    const float* Wl2 = (const float*)d_in[8];
    const float* bl2 = (const float*)d_in[9];
    const float* Wr2 = (const float*)d_in[10];

    int N = in_sizes[0] / F;
    int E = in_sizes[1] / 2;
    const int* src = ei;
    const int* dst = ei + E;

    float* out = (float*)d_out;
    float* h2  = out + (size_t)2 * N * CC;   // layout: out | out | h2

    void* p;
    cudaGetSymbolAddress(&p, g_y);  float* yb = (float*)p;
    cudaGetSymbolAddress(&p, g_r);  float* rb = (float*)p;
    cudaGetSymbolAddress(&p, g_h);  float* hb = (float*)p;

    // ---- CSR build ----
    k_init<<<(N + 255) / 256, 256>>>(N);
    k_hist<<<(E + 255) / 256, 256>>>(dst, E);
    int nScanBlocks = (N + SCAN_B - 1) / SCAN_B;
    k_scan1<<<nScanBlocks, SCAN_B>>>(N);
    k_scan2<<<1, 256>>>(nScanBlocks);
    k_scan3<<<nScanBlocks, SCAN_B>>>(N);
    k_fill<<<(E + 255) / 256, 256>>>(src, dst, E);

    int gemmBlocks = (N + BM - 1) / BM;
    int warpBlocks = (N * 32 + 255) / 256;

    // ---- layer 0: y = x@Wl0, r = x@Wr0 ; h = relu(agg(y)*invd + bl0 + r) ----
    k_sgemm<<<dim3(gemmBlocks, 2), 256>>>(x, Wl0, Wr0, yb, rb, N);
    k_agg128<<<warpBlocks, 256>>>(yb, rb, bl0, hb, N, 1);

    // ---- layer 1: y = h@Wl1, r = h@Wr1 ; h2 = agg(y)*invd + bl1 + r ----
    k_sgemm<<<dim3(gemmBlocks, 2), 256>>>(hb, Wl1, Wr1, yb, rb, N);
    k_agg128<<<warpBlocks, 256>>>(yb, rb, bl1, h2, N, 0);

    // ---- layer 2: z = h2@Wl2, r2 = h2@Wr2 ; out = agg(z)*invd + bl2 + r2 ----
    k_gemm_small<<<warpBlocks, 256>>>(h2, Wl2, Wr2, N);
    k_agg4<<<warpBlocks, 256>>>(bl2, out, N);
}

// round 4
// speedup vs baseline: 1.0544x; 1.0544x over previous
#include <cuda_runtime.h>
#include <cuda_bf16.h>
#include <cstdint>

// Problem constants (fixed by the dataset)
#define NN 50000
#define EE 800000
#define F 128
#define CC 4

// ---------------- device scratch (no allocation allowed) ----------------
__device__ __align__(128) int   g_cnt[NN];
__device__ __align__(128) int   g_fill[NN];
__device__ __align__(128) int   g_ptr[NN + 1];
__device__ __align__(128) int   g_idx[EE];
__device__ __align__(128) int   g_partial[NN];
__device__ __align__(128) int   g_bsum[256];
__device__ __align__(128) float g_invd[NN];
__device__ __align__(128) float g_y[(size_t)NN * F];
__device__ __align__(128) float g_r[(size_t)NN * F];
__device__ __align__(128) float g_h[(size_t)NN * F];
__device__ __align__(128) float g_z[(size_t)NN * CC];
__device__ __align__(128) float g_r2[(size_t)NN * CC];
// packed bf16 weights in mma B-fragment layout: [kk(=k/2)][n] uint32 = (bf16 k, bf16 k+1)
// 4 matrices: Wl0, Wr0, Wl1, Wr1; hi and lo split terms.
__device__ __align__(128) uint32_t g_wp_hi[4][64 * F];
__device__ __align__(128) uint32_t g_wp_lo[4][64 * F];

// ---------------- CSR build ----------------
__global__ void k_init(int n) {
    int i = blockIdx.x * blockDim.x + threadIdx.x;
    if (i < n) { g_cnt[i] = 0; g_fill[i] = 0; }
}

__global__ void k_hist(const int* __restrict__ dst, int e) {
    int i = blockIdx.x * blockDim.x + threadIdx.x;
    if (i < e) atomicAdd(&g_cnt[dst[i]], 1);
}

#define SCAN_B 512
__global__ void k_scan1(int n) {
    __shared__ int s[SCAN_B];
    int i = blockIdx.x * SCAN_B + threadIdx.x;
    int v = (i < n) ? g_cnt[i] : 0;
    s[threadIdx.x] = v;
    __syncthreads();
    #pragma unroll
    for (int off = 1; off < SCAN_B; off <<= 1) {
        int t = (threadIdx.x >= off) ? s[threadIdx.x - off] : 0;
        __syncthreads();
        s[threadIdx.x] += t;
        __syncthreads();
    }
    if (i < n) g_partial[i] = s[threadIdx.x];
    if (threadIdx.x == SCAN_B - 1) g_bsum[blockIdx.x] = s[threadIdx.x];
}

__global__ void k_scan2(int nb) {
    __shared__ int s[256];
    int v = (threadIdx.x < nb) ? g_bsum[threadIdx.x] : 0;
    s[threadIdx.x] = v;
    __syncthreads();
    #pragma unroll
    for (int off = 1; off < 256; off <<= 1) {
        int t = (threadIdx.x >= off) ? s[threadIdx.x - off] : 0;
        __syncthreads();
        s[threadIdx.x] += t;
        __syncthreads();
    }
    if (threadIdx.x < nb) g_bsum[threadIdx.x] = s[threadIdx.x] - v;  // exclusive
}

__global__ void k_scan3(int n) {
    int i = blockIdx.x * SCAN_B + threadIdx.x;
    if (i < n) {
        int inc = g_partial[i] + g_bsum[blockIdx.x];
        g_ptr[i + 1] = inc;
        int c = g_cnt[i];
        g_invd[i] = (c > 0) ? (1.0f / (float)c) : 0.0f;
        if (i == 0) g_ptr[0] = 0;
    }
}

__global__ void k_fill(const int* __restrict__ src, const int* __restrict__ dst, int e) {
    int i = blockIdx.x * blockDim.x + threadIdx.x;
    if (i < e) {
        int d = dst[i];
        int p = g_ptr[d] + atomicAdd(&g_fill[d], 1);
        g_idx[p] = src[i];
    }
}

// ---------------- weight prep: W[k][n] fp32 -> packed bf16 hi/lo, B-frag layout ----
__device__ __forceinline__ uint32_t pack_bf2(float a, float b) {
    __nv_bfloat16 ha = __float2bfloat16(a);
    __nv_bfloat16 hb = __float2bfloat16(b);
    return (uint32_t)__bfloat16_as_ushort(ha) | ((uint32_t)__bfloat16_as_ushort(hb) << 16);
}

__global__ void k_prepW(const float* __restrict__ W,
                        uint32_t* __restrict__ hi, uint32_t* __restrict__ lo) {
    int i = blockIdx.x * blockDim.x + threadIdx.x;  // 0..8191
    if (i >= 64 * F) return;
    int kk = i >> 7, n = i & 127;
    float w0 = W[(2 * kk) * F + n];
    float w1 = W[(2 * kk + 1) * F + n];
    __nv_bfloat16 h0 = __float2bfloat16(w0), h1 = __float2bfloat16(w1);
    float r0 = w0 - __bfloat162float(h0);
    float r1 = w1 - __bfloat162float(h1);
    hi[i] = (uint32_t)__bfloat16_as_ushort(h0) | ((uint32_t)__bfloat16_as_ushort(h1) << 16);
    lo[i] = pack_bf2(r0, r1);
}

// ---------------- mma.sync bf16 GEMM (3-term split): Y = A @ W -------------------
// Block: 128 rows x 128 cols, 256 threads (8 warps: 4 row-groups x 2 col-groups).
// blockIdx.y selects (Wl -> Yl) or (Wr -> Yr).
//
// Smem layout (bytes):
//   AHI  [128 rows][272B]  (128 bf16 = 256B + 16B pad)   34816
//   ALO  same                                            34816
//   BHI  [64 kk][136 words] (128 uint32 + 8 pad)         34816
//   BLO  same                                            34816
#define SM_AHI 0
#define SM_ALO 34816
#define SM_BHI 69632
#define SM_BLO 104448
#define SM_GEMM_TOTAL 139264
#define A_STRIDE_B 272
#define B_STRIDE_W 136

__device__ __forceinline__ void mma_bf16(float* c, const uint32_t* a, const uint32_t* b) {
    asm volatile(
        "mma.sync.aligned.m16n8k16.row.col.f32.bf16.bf16.f32 "
        "{%0,%1,%2,%3}, {%4,%5,%6,%7}, {%8,%9}, {%0,%1,%2,%3};"
        : "+f"(c[0]), "+f"(c[1]), "+f"(c[2]), "+f"(c[3])
        : "r"(a[0]), "r"(a[1]), "r"(a[2]), "r"(a[3]), "r"(b[0]), "r"(b[1]));
}

__global__ __launch_bounds__(256, 1)
void k_mma(const float* __restrict__ A,
           const uint32_t* __restrict__ wlhi, const uint32_t* __restrict__ wllo,
           const uint32_t* __restrict__ wrhi, const uint32_t* __restrict__ wrlo,
           float* __restrict__ Yl, float* __restrict__ Yr, int M) {
    extern __shared__ char smem[];
    const int tid = threadIdx.x;
    const int wid = tid >> 5;
    const int lane = tid & 31;
    const int rowBase = blockIdx.x * 128;

    const uint32_t* Whi = blockIdx.y ? wrhi : wlhi;
    const uint32_t* Wlo = blockIdx.y ? wrlo : wllo;
    float* Y = blockIdx.y ? Yr : Yl;

    // ---- load & split A tile ----
    for (int idx = tid; idx < 128 * 32; idx += 256) {
        int row = idx >> 5;
        int c4 = (idx & 31) * 4;
        float4 v = make_float4(0.f, 0.f, 0.f, 0.f);
        int gr = rowBase + row;
        if (gr < M) v = *(const float4*)(A + (size_t)gr * F + c4);
        float hx = __bfloat162float(__float2bfloat16(v.x));
        float hy = __bfloat162float(__float2bfloat16(v.y));
        float hz = __bfloat162float(__float2bfloat16(v.z));
        float hw = __bfloat162float(__float2bfloat16(v.w));
        uint32_t hi0 = pack_bf2(v.x, v.y);
        uint32_t hi1 = pack_bf2(v.z, v.w);
        uint32_t lo0 = pack_bf2(v.x - hx, v.y - hy);
        uint32_t lo1 = pack_bf2(v.z - hz, v.w - hw);
        uint32_t off = (uint32_t)row * A_STRIDE_B + (uint32_t)c4 * 2;
        *(uint2*)(smem + SM_AHI + off) = make_uint2(hi0, hi1);
        *(uint2*)(smem + SM_ALO + off) = make_uint2(lo0, lo1);
    }
    // ---- load W tiles (packed uint32 [kk][n]) ----
    for (int idx = tid; idx < 64 * 32; idx += 256) {
        int kk = idx >> 5;
        int c4 = (idx & 31) * 4;
        uint4 vh = *(const uint4*)(Whi + kk * F + c4);
        uint4 vl = *(const uint4*)(Wlo + kk * F + c4);
        uint32_t off = ((uint32_t)kk * B_STRIDE_W + (uint32_t)c4) * 4;
        *(uint4*)(smem + SM_BHI + off) = vh;
        *(uint4*)(smem + SM_BLO + off) = vl;
    }
    __syncthreads();

    const int m0 = (wid & 3) * 32;
    const int n0 = (wid >> 2) * 64;

    float acc[2][8][4];
    #pragma unroll
    for (int t = 0; t < 2; t++)
        #pragma unroll
        for (int j = 0; j < 8; j++)
            #pragma unroll
            for (int q = 0; q < 4; q++) acc[t][j][q] = 0.0f;

    const int r_lo = lane >> 2;
    const int kc = lane & 3;

    #pragma unroll
    for (int ks = 0; ks < 8; ks++) {
        const int k0 = ks * 16;
        uint32_t ah[2][4], al[2][4];
        #pragma unroll
        for (int t = 0; t < 2; t++) {
            uint32_t base = (uint32_t)(m0 + t * 16 + r_lo) * A_STRIDE_B + (uint32_t)(k0 + 2 * kc) * 2;
            ah[t][0] = *(const uint32_t*)(smem + SM_AHI + base);
            ah[t][1] = *(const uint32_t*)(smem + SM_AHI + base + 8 * A_STRIDE_B);
            ah[t][2] = *(const uint32_t*)(smem + SM_AHI + base + 16);
            ah[t][3] = *(const uint32_t*)(smem + SM_AHI + base + 8 * A_STRIDE_B + 16);
            al[t][0] = *(const uint32_t*)(smem + SM_ALO + base);
            al[t][1] = *(const uint32_t*)(smem + SM_ALO + base + 8 * A_STRIDE_B);
            al[t][2] = *(const uint32_t*)(smem + SM_ALO + base + 16);
            al[t][3] = *(const uint32_t*)(smem + SM_ALO + base + 8 * A_STRIDE_B + 16);
        }
        uint32_t bh[8][2], bl[8][2];
        const int kk0 = ks * 8;
        #pragma unroll
        for (int j = 0; j < 8; j++) {
            uint32_t off = ((uint32_t)(kk0 + kc) * B_STRIDE_W + (uint32_t)(n0 + j * 8 + r_lo)) * 4;
            bh[j][0] = *(const uint32_t*)(smem + SM_BHI + off);
            bh[j][1] = *(const uint32_t*)(smem + SM_BHI + off + 4 * B_STRIDE_W * 4);
            bl[j][0] = *(const uint32_t*)(smem + SM_BLO + off);
            bl[j][1] = *(const uint32_t*)(smem + SM_BLO + off + 4 * B_STRIDE_W * 4);
        }
        #pragma unroll
        for (int t = 0; t < 2; t++)
            #pragma unroll
            for (int j = 0; j < 8; j++) mma_bf16(acc[t][j], ah[t], bh[j]);
        #pragma unroll
        for (int t = 0; t < 2; t++)
            #pragma unroll
            for (int j = 0; j < 8; j++) mma_bf16(acc[t][j], al[t], bh[j]);
        #pragma unroll
        for (int t = 0; t < 2; t++)
            #pragma unroll
            for (int j = 0; j < 8; j++) mma_bf16(acc[t][j], ah[t], bl[j]);
    }

    // ---- epilogue ----
    #pragma unroll
    for (int t = 0; t < 2; t++) {
        int row0 = rowBase + m0 + t * 16 + r_lo;
        #pragma unroll
        for (int j = 0; j < 8; j++) {
            int col = n0 + j * 8 + 2 * kc;
            if (row0 < M)
                *(float2*)(Y + (size_t)row0 * F + col) = make_float2(acc[t][j][0], acc[t][j][1]);
            if (row0 + 8 < M)
                *(float2*)(Y + (size_t)(row0 + 8) * F + col) = make_float2(acc[t][j][2], acc[t][j][3]);
        }
    }
}

// ---------------- 128-wide aggregation, fused epilogue ----------------
__global__ void k_agg128(const float* __restrict__ Y, const float* __restrict__ R,
                         const float* __restrict__ bias, float* __restrict__ O,
                         int n, int doRelu) {
    int gwarp = (blockIdx.x * blockDim.x + threadIdx.x) >> 5;
    int lane = threadIdx.x & 31;
    if (gwarp >= n) return;
    int s = g_ptr[gwarp], e = g_ptr[gwarp + 1];
    float4 a0 = make_float4(0.f, 0.f, 0.f, 0.f);
    float4 a1 = make_float4(0.f, 0.f, 0.f, 0.f);
    int i = s;
    for (; i + 1 < e; i += 2) {
        int n0 = g_idx[i], n1 = g_idx[i + 1];
        float4 v0 = *(const float4*)(Y + (size_t)n0 * F + lane * 4);
        float4 v1 = *(const float4*)(Y + (size_t)n1 * F + lane * 4);
        a0.x += v0.x; a0.y += v0.y; a0.z += v0.z; a0.w += v0.w;
        a1.x += v1.x; a1.y += v1.y; a1.z += v1.z; a1.w += v1.w;
    }
    if (i < e) {
        int n0 = g_idx[i];
        float4 v0 = *(const float4*)(Y + (size_t)n0 * F + lane * 4);
        a0.x += v0.x; a0.y += v0.y; a0.z += v0.z; a0.w += v0.w;
    }
    a0.x += a1.x; a0.y += a1.y; a0.z += a1.z; a0.w += a1.w;
    float id = g_invd[gwarp];
    float4 rv = *(const float4*)(R + (size_t)gwarp * F + lane * 4);
    float4 bv = *(const float4*)(bias + lane * 4);
    float4 o;
    o.x = a0.x * id + bv.x + rv.x;
    o.y = a0.y * id + bv.y + rv.y;
    o.z = a0.z * id + bv.z + rv.z;
    o.w = a0.w * id + bv.w + rv.w;
    if (doRelu) {
        o.x = fmaxf(o.x, 0.f); o.y = fmaxf(o.y, 0.f);
        o.z = fmaxf(o.z, 0.f); o.w = fmaxf(o.w, 0.f);
    }
    *(float4*)(O + (size_t)gwarp * F + lane * 4) = o;
}

// ---------------- small GEMM: Z[M,4] = H[M,128] @ Wl2, R2 = H @ Wr2 ----------------
__global__ void k_gemm_small(const float* __restrict__ H,
                             const float* __restrict__ Wl, const float* __restrict__ Wr,
                             int M) {
    __shared__ float sWl[F * CC];
    __shared__ float sWr[F * CC];
    int tid = threadIdx.x;
    for (int i = tid; i < F * CC; i += blockDim.x) { sWl[i] = Wl[i]; sWr[i] = Wr[i]; }
    __syncthreads();
    int gwarp = (blockIdx.x * blockDim.x + tid) >> 5;
    int lane = tid & 31;
    if (gwarp >= M) return;
    float4 h = *(const float4*)(H + (size_t)gwarp * F + lane * 4);
    float hv[4] = {h.x, h.y, h.z, h.w};
    float zl[4] = {0.f, 0.f, 0.f, 0.f};
    float zr[4] = {0.f, 0.f, 0.f, 0.f};
    #pragma unroll
    for (int kk = 0; kk < 4; kk++) {
        int k = lane * 4 + kk;
        #pragma unroll
        for (int j = 0; j < 4; j++) {
            zl[j] += hv[kk] * sWl[k * CC + j];
            zr[j] += hv[kk] * sWr[k * CC + j];
        }
    }
    #pragma unroll
    for (int off = 16; off > 0; off >>= 1) {
        #pragma unroll
        for (int j = 0; j < 4; j++) {
            zl[j] += __shfl_down_sync(0xFFFFFFFFu, zl[j], off);
            zr[j] += __shfl_down_sync(0xFFFFFFFFu, zr[j], off);
        }
    }
    if (lane == 0) {
        *(float4*)(g_z  + (size_t)gwarp * CC) = make_float4(zl[0], zl[1], zl[2], zl[3]);
        *(float4*)(g_r2 + (size_t)gwarp * CC) = make_float4(zr[0], zr[1], zr[2], zr[3]);
    }
}

// ---------------- 4-wide aggregation + final epilogue; writes out twice ----------------
__global__ void k_agg4(const float* __restrict__ b2, float* __restrict__ out, int n) {
    int gwarp = (blockIdx.x * blockDim.x + threadIdx.x) >> 5;
    int lane = threadIdx.x & 31;
    if (gwarp >= n) return;
    int s = g_ptr[gwarp], e = g_ptr[gwarp + 1];
    float4 acc = make_float4(0.f, 0.f, 0.f, 0.f);
    for (int i = s + lane; i < e; i += 32) {
        int nb = g_idx[i];
        float4 z = *(const float4*)(g_z + (size_t)nb * CC);
        acc.x += z.x; acc.y += z.y; acc.z += z.z; acc.w += z.w;
    }
    #pragma unroll
    for (int off = 16; off > 0; off >>= 1) {
        acc.x += __shfl_xor_sync(0xFFFFFFFFu, acc.x, off);
        acc.y += __shfl_xor_sync(0xFFFFFFFFu, acc.y, off);
        acc.z += __shfl_xor_sync(0xFFFFFFFFu, acc.z, off);
        acc.w += __shfl_xor_sync(0xFFFFFFFFu, acc.w, off);
    }
    if (lane == 0) {
        float id = g_invd[gwarp];
        float4 r = *(const float4*)(g_r2 + (size_t)gwarp * CC);
        float4 b = *(const float4*)(b2);
        float4 o;
        o.x = acc.x * id + b.x + r.x;
        o.y = acc.y * id + b.y + r.y;
        o.z = acc.z * id + b.z + r.z;
        o.w = acc.w * id + b.w + r.w;
        *(float4*)(out + (size_t)gwarp * CC) = o;
        *(float4*)(out + (size_t)n * CC + (size_t)gwarp * CC) = o;
    }
}

// ---------------- launch ----------------
extern "C" void kernel_launch(void* const* d_in, const int* in_sizes, int n_in,
                              void* d_out, int out_size) {
    const float* x   = (const float*)d_in[0];
    const int*   ei  = (const int*)d_in[1];
    const float* Wl0 = (const float*)d_in[2];
    const float* bl0 = (const float*)d_in[3];
    const float* Wr0 = (const float*)d_in[4];
    const float* Wl1 = (const float*)d_in[5];
    const float* bl1 = (const float*)d_in[6];
    const float* Wr1 = (const float*)d_in[7];
    const float* Wl2 = (const float*)d_in[8];
    const float* bl2 = (const float*)d_in[9];
    const float* Wr2 = (const float*)d_in[10];

    int N = in_sizes[0] / F;
    int E = in_sizes[1] / 2;
    const int* src = ei;
    const int* dst = ei + E;

    float* out = (float*)d_out;
    float* h2  = out + (size_t)2 * N * CC;   // layout: out | out | h2

    void* p;
    cudaGetSymbolAddress(&p, g_y);  float* yb = (float*)p;
    cudaGetSymbolAddress(&p, g_r);  float* rb = (float*)p;
    cudaGetSymbolAddress(&p, g_h);  float* hb = (float*)p;
    cudaGetSymbolAddress(&p, g_wp_hi); uint32_t* whi = (uint32_t*)p;
    cudaGetSymbolAddress(&p, g_wp_lo); uint32_t* wlo = (uint32_t*)p;

    cudaFuncSetAttribute(k_mma, cudaFuncAttributeMaxDynamicSharedMemorySize, SM_GEMM_TOTAL);

    // ---- weight prep (4 small launches) ----
    const float* wmats[4] = { Wl0, Wr0, Wl1, Wr1 };
    for (int m = 0; m < 4; m++)
        k_prepW<<<(64 * F + 255) / 256, 256>>>(wmats[m], whi + (size_t)m * 64 * F,
                                               wlo + (size_t)m * 64 * F);

    // ---- CSR build ----
    k_init<<<(N + 255) / 256, 256>>>(N);
    k_hist<<<(E + 255) / 256, 256>>>(dst, E);
    int nScanBlocks = (N + SCAN_B - 1) / SCAN_B;
    k_scan1<<<nScanBlocks, SCAN_B>>>(N);
    k_scan2<<<1, 256>>>(nScanBlocks);
    k_scan3<<<nScanBlocks, SCAN_B>>>(N);
    k_fill<<<(E + 255) / 256, 256>>>(src, dst, E);

    int gemmBlocks = (N + 127) / 128;
    int warpBlocks = (N * 32 + 255) / 256;

    // ---- layer 0: y = x@Wl0, r = x@Wr0 ; h = relu(agg(y)*invd + bl0 + r) ----
    k_mma<<<dim3(gemmBlocks, 2), 256, SM_GEMM_TOTAL>>>(
        x, whi + (size_t)0 * 64 * F, wlo + (size_t)0 * 64 * F,
           whi + (size_t)1 * 64 * F, wlo + (size_t)1 * 64 * F, yb, rb, N);
    k_agg128<<<warpBlocks, 256>>>(yb, rb, bl0, hb, N, 1);

    // ---- layer 1: y = h@Wl1, r = h@Wr1 ; h2 = agg(y)*invd + bl1 + r ----
    k_mma<<<dim3(gemmBlocks, 2), 256, SM_GEMM_TOTAL>>>(
        hb, whi + (size_t)2 * 64 * F, wlo + (size_t)2 * 64 * F,
            whi + (size_t)3 * 64 * F, wlo + (size_t)3 * 64 * F, yb, rb, N);
    k_agg128<<<warpBlocks, 256>>>(yb, rb, bl1, h2, N, 0);

    // ---- layer 2: z = h2@Wl2, r2 = h2@Wr2 ; out = agg(z)*invd + bl2 + r2 ----
    k_gemm_small<<<warpBlocks, 256>>>(h2, Wl2, Wr2, N);
    k_agg4<<<warpBlocks, 256>>>(bl2, out, N);
}